// round 8
// baseline (speedup 1.0000x reference)
#include <cuda_runtime.h>
#include <cstdint>

// CAModel on GB300: block = 256 contiguous px of one row, 512 threads, 1 CTA/SM.
// Single-pass GEMM1 (8px x 8hid register tiles), full H in smem (permuted rows),
// GEMM2 4-way split-K (8px x 4ko), packed f32x2 FMA throughout (exact fp32).

#define HPITCH 260                       // halo row pitch (floats)
#define YPITCH 264                       // ys row pitch
#define HP     268                       // H row pitch (268*4 % 128 = 48 -> bank spread)
#define YS_OFF 0                         // ys [48][YPITCH]; rows 16..47 reused as scratch
#define W0_OFF (48 * YPITCH)             // w0s [48][128]  (w0s[k][o])
#define W1_OFF (W0_OFF + 48 * 128)       // w1s [128][16]  (physical-row permuted)
#define B0_OFF (W1_OFF + 128 * 16)       // b0s [128]
#define U_OFF  (B0_OFF + 128)            // union: halo [16][3][HPITCH] / H [128][HP]
#define SMEM_FLOATS (U_OFF + 128 * HP)   // 55296 floats
#define SMEM_BYTES  (SMEM_FLOATS * 4)    // 221184 B

typedef unsigned long long u64;

__device__ __forceinline__ u64 pack2(float lo, float hi) {
    u64 r;
    asm("mov.b64 %0, {%1, %2};" : "=l"(r) : "r"(__float_as_uint(lo)), "r"(__float_as_uint(hi)));
    return r;
}
__device__ __forceinline__ void unpack2(u64 v, float& lo, float& hi) {
    uint32_t a, b;
    asm("mov.b64 {%0, %1}, %2;" : "=r"(a), "=r"(b) : "l"(v));
    lo = __uint_as_float(a); hi = __uint_as_float(b);
}
__device__ __forceinline__ u64 fma2(u64 a, u64 b, u64 c) {
    u64 r;
    asm("fma.rn.f32x2 %0, %1, %2, %3;" : "=l"(r) : "l"(a), "l"(b), "l"(c));
    return r;
}
__device__ __forceinline__ u64 add2(u64 a, u64 b) {
    u64 r;
    asm("add.rn.f32x2 %0, %1, %2;" : "=l"(r) : "l"(a), "l"(b));
    return r;
}

__global__ void __launch_bounds__(512, 1)
ca_kernel(const float* __restrict__ x, const float* __restrict__ w0,
          const float* __restrict__ b0, const float* __restrict__ w1,
          const float* __restrict__ ru, float* __restrict__ out)
{
    extern __shared__ float sm[];
    float* ys  = sm + YS_OFF;
    float* w0s = sm + W0_OFF;
    float* w1s = sm + W1_OFF;
    float* b0s = sm + B0_OFF;
    float* us  = sm + U_OFF;   // halo, later H

    const int tid    = threadIdx.x;
    const int colblk = blockIdx.x;   // 0..1
    const int row    = blockIdx.y;   // 0..511
    const int b      = blockIdx.z;   // 0..3
    const int col0   = colblk * 256;

    // ---------- halo: us[ch][r][j], j -> gcol = col0 + j - 1 (258 cols used) ----------
    {
        const long xbase = (long)b * 16 * 512 * 512;
        for (int idx = tid; idx < 16 * 3 * HPITCH; idx += 512) {
            int col = idx % HPITCH;
            int t   = idx / HPITCH;
            int r   = t % 3;
            int ch  = t / 3;
            int gcol = col0 + col - 1;
            int grow = row + r - 1;
            float v = 0.0f;
            if (gcol >= 0 && gcol < 512 && grow >= 0 && grow < 512)
                v = x[xbase + ((long)ch * 512 + grow) * 512 + gcol];
            us[idx] = v;
        }
    }
    __syncthreads();

    // ---------- features: ys rows 0..15 = x, 16..31 = gx, 32..47 = gy ----------
    for (int idx = tid; idx < 16 * 256; idx += 512) {
        int p  = idx & 255;
        int ch = idx >> 8;
        const float* h0 = us + (ch * 3 + 0) * HPITCH + p;
        const float* h1 = us + (ch * 3 + 1) * HPITCH + p;
        const float* h2 = us + (ch * 3 + 2) * HPITCH + p;
        float a00 = h0[0], a01 = h0[1], a02 = h0[2];
        float a10 = h1[0], a11 = h1[1], a12 = h1[2];
        float a20 = h2[0], a21 = h2[1], a22 = h2[2];
        float gx = (a02 - a00) + 2.0f * (a12 - a10) + (a22 - a20);
        float gy = (a20 + 2.0f * a21 + a22) - (a00 + 2.0f * a01 + a02);
        ys[ch * YPITCH + p]        = a11;
        ys[(16 + ch) * YPITCH + p] = gx;
        ys[(32 + ch) * YPITCH + p] = gy;
    }
    // weights into smem
    for (int idx = tid; idx < 128 * 48; idx += 512) {
        int o = idx / 48, k = idx % 48;
        w0s[k * 128 + o] = w0[idx];
    }
    for (int idx = tid; idx < 16 * 128; idx += 512) {
        int ko = idx >> 7, L = idx & 127;
        int P = (L & 7) * 16 + (L >> 3);       // physical H row for logical hid L
        w1s[P * 16 + ko] = w1[idx];
    }
    if (tid < 128) b0s[tid] = b0[tid];
    __syncthreads();

    // ---------- GEMM1: H[hid][px] = relu(b0 + sum_k y[k][px] * w0[hid][k]) ----------
    {
        const int og  = tid & 15;     // 8 hidden each: hid = og*8 + i
        const int pg  = tid >> 4;     // 0..31, 8 px each
        const int pg8 = pg * 8;
        const int hb  = og * 8;

        u64 acc2[4][8];
        {
            float4 ba = *(const float4*)&b0s[hb];
            float4 bb = *(const float4*)&b0s[hb + 4];
            float bv[8] = {ba.x, ba.y, ba.z, ba.w, bb.x, bb.y, bb.z, bb.w};
#pragma unroll
            for (int i = 0; i < 8; ++i) {
                u64 bp = pack2(bv[i], bv[i]);
#pragma unroll
                for (int pp = 0; pp < 4; ++pp) acc2[pp][i] = bp;
            }
        }
#pragma unroll 4
        for (int k = 0; k < 48; ++k) {
            ulonglong2 ya = *(const ulonglong2*)&ys[k * YPITCH + pg8];
            ulonglong2 yb = *(const ulonglong2*)&ys[k * YPITCH + pg8 + 4];
            u64 yq[4] = {ya.x, ya.y, yb.x, yb.y};
            float4 wa = *(const float4*)&w0s[k * 128 + hb];
            float4 wb = *(const float4*)&w0s[k * 128 + hb + 4];
            float wv[8] = {wa.x, wa.y, wa.z, wa.w, wb.x, wb.y, wb.z, wb.w};
            u64 wq[8];
#pragma unroll
            for (int i = 0; i < 8; ++i) wq[i] = pack2(wv[i], wv[i]);
#pragma unroll
            for (int pp = 0; pp < 4; ++pp)
#pragma unroll
                for (int i = 0; i < 8; ++i)
                    acc2[pp][i] = fma2(yq[pp], wq[i], acc2[pp][i]);
        }
        // relu + store H at physical row P = i*16 + og (lanes hit consecutive rows)
#pragma unroll
        for (int i = 0; i < 8; ++i) {
            float p0,p1,p2,p3,p4,p5,p6,p7;
            unpack2(acc2[0][i], p0, p1);
            unpack2(acc2[1][i], p2, p3);
            unpack2(acc2[2][i], p4, p5);
            unpack2(acc2[3][i], p6, p7);
            float4 v0, v1;
            v0.x = fmaxf(p0, 0.0f); v0.y = fmaxf(p1, 0.0f);
            v0.z = fmaxf(p2, 0.0f); v0.w = fmaxf(p3, 0.0f);
            v1.x = fmaxf(p4, 0.0f); v1.y = fmaxf(p5, 0.0f);
            v1.z = fmaxf(p6, 0.0f); v1.w = fmaxf(p7, 0.0f);
            int P = i * 16 + og;
            *(float4*)&us[P * HP + pg8]     = v0;
            *(float4*)&us[P * HP + pg8 + 4] = v1;
        }
    }
    __syncthreads();

    // ---------- GEMM2: update[px][ko] = sum_hid H[hid][px] * w1[ko][hid] ----------
    const int kog = tid & 3;          // 4 out-ch each: ko = kog*4 + i
    const int os  = (tid >> 2) & 3;   // 4-way split over physical H rows
    const int pg2 = tid >> 4;         // 0..31, 8 px each
    const int pb  = pg2 * 8;

    u64 u2[4][4];
#pragma unroll
    for (int pp = 0; pp < 4; ++pp)
#pragma unroll
        for (int i = 0; i < 4; ++i) u2[pp][i] = 0ull;

#pragma unroll 4
    for (int j = 0; j < 32; ++j) {
        int P = os * 32 + j;
        ulonglong2 h0 = *(const ulonglong2*)&us[P * HP + pb];
        ulonglong2 h1 = *(const ulonglong2*)&us[P * HP + pb + 4];
        u64 hq[4] = {h0.x, h0.y, h1.x, h1.y};
        float4 wv = *(const float4*)&w1s[P * 16 + kog * 4];
        u64 wq[4] = {pack2(wv.x, wv.x), pack2(wv.y, wv.y),
                     pack2(wv.z, wv.z), pack2(wv.w, wv.w)};
#pragma unroll
        for (int pp = 0; pp < 4; ++pp)
#pragma unroll
            for (int i = 0; i < 4; ++i)
                u2[pp][i] = fma2(hq[pp], wq[i], u2[pp][i]);
    }

    // ---------- 4-way split-K reduction via scratch (ys rows 16..47, dead now) ----------
    u64* scrA = (u64*)(ys + 16 * YPITCH);          // 128 slots x 16 u64
    u64* scrB = scrA + 128 * 16;
    const int slot = (pg2 * 4 + kog) * 16;

    if (os == 1) {
#pragma unroll
        for (int pp = 0; pp < 4; ++pp)
#pragma unroll
            for (int i = 0; i < 4; ++i) scrA[slot + pp * 4 + i] = u2[pp][i];
    } else if (os == 3) {
#pragma unroll
        for (int pp = 0; pp < 4; ++pp)
#pragma unroll
            for (int i = 0; i < 4; ++i) scrB[slot + pp * 4 + i] = u2[pp][i];
    }
    __syncthreads();
    if (os == 0) {
#pragma unroll
        for (int pp = 0; pp < 4; ++pp)
#pragma unroll
            for (int i = 0; i < 4; ++i)
                u2[pp][i] = add2(u2[pp][i], scrA[slot + pp * 4 + i]);
    } else if (os == 2) {
#pragma unroll
        for (int pp = 0; pp < 4; ++pp)
#pragma unroll
            for (int i = 0; i < 4; ++i)
                u2[pp][i] = add2(u2[pp][i], scrB[slot + pp * 4 + i]);
    }
    __syncthreads();
    if (os == 2) {
#pragma unroll
        for (int pp = 0; pp < 4; ++pp)
#pragma unroll
            for (int i = 0; i < 4; ++i) scrA[slot + pp * 4 + i] = u2[pp][i];
    }
    __syncthreads();

    if (os == 0) {
#pragma unroll
        for (int pp = 0; pp < 4; ++pp)
#pragma unroll
            for (int i = 0; i < 4; ++i)
                u2[pp][i] = add2(u2[pp][i], scrA[slot + pp * 4 + i]);

        float u[8][4];
#pragma unroll
        for (int i = 0; i < 4; ++i) {
            unpack2(u2[0][i], u[0][i], u[1][i]);
            unpack2(u2[1][i], u[2][i], u[3][i]);
            unpack2(u2[2][i], u[4][i], u[5][i]);
            unpack2(u2[3][i], u[6][i], u[7][i]);
        }

        // ---------- epilogue: out = x + update * (rand_u > 0.5) ----------
        const long rubase = ((long)b * 512 + row) * 512 + col0 + pb;
        float4 r0 = *(const float4*)&ru[rubase];
        float4 r1 = *(const float4*)&ru[rubase + 4];
        float m[8];
        m[0] = r0.x > 0.5f ? 1.0f : 0.0f;  m[1] = r0.y > 0.5f ? 1.0f : 0.0f;
        m[2] = r0.z > 0.5f ? 1.0f : 0.0f;  m[3] = r0.w > 0.5f ? 1.0f : 0.0f;
        m[4] = r1.x > 0.5f ? 1.0f : 0.0f;  m[5] = r1.y > 0.5f ? 1.0f : 0.0f;
        m[6] = r1.z > 0.5f ? 1.0f : 0.0f;  m[7] = r1.w > 0.5f ? 1.0f : 0.0f;
#pragma unroll
        for (int ki = 0; ki < 4; ++ki) {
            int ko = kog * 4 + ki;
            float4 xc0 = *(const float4*)&ys[ko * YPITCH + pb];
            float4 xc1 = *(const float4*)&ys[ko * YPITCH + pb + 4];
            float4 o0, o1;
            o0.x = xc0.x + u[0][ki] * m[0];
            o0.y = xc0.y + u[1][ki] * m[1];
            o0.z = xc0.z + u[2][ki] * m[2];
            o0.w = xc0.w + u[3][ki] * m[3];
            o1.x = xc1.x + u[4][ki] * m[4];
            o1.y = xc1.y + u[5][ki] * m[5];
            o1.z = xc1.z + u[6][ki] * m[6];
            o1.w = xc1.w + u[7][ki] * m[7];
            long oidx = (((long)b * 16 + ko) * 512 + row) * 512 + col0 + pb;
            *(float4*)&out[oidx]     = o0;
            *(float4*)&out[oidx + 4] = o1;
        }
    }
}

extern "C" void kernel_launch(void* const* d_in, const int* in_sizes, int n_in,
                              void* d_out, int out_size) {
    const float* x  = (const float*)d_in[0];
    const float* w0 = (const float*)d_in[1];
    const float* b0 = (const float*)d_in[2];
    const float* w1 = (const float*)d_in[3];
    const float* ru = (const float*)d_in[4];
    float* out = (float*)d_out;

    cudaFuncSetAttribute(ca_kernel, cudaFuncAttributeMaxDynamicSharedMemorySize, SMEM_BYTES);
    dim3 grid(2, 512, 4);   // (col-block of 256, row, batch)
    ca_kernel<<<grid, 512, SMEM_BYTES>>>(x, w0, b0, w1, ru, out);
}